// round 6
// baseline (speedup 1.0000x reference)
#include <cuda_runtime.h>

// Ricker scan, chunk-parallel via contraction warm-up (round 6: 1-warp blocks).
//   n_{i+1} = n_i * exp(alpha*(1 - beta*n_i + f_i)) + sigma*eps_i
// L=32-step chunks, W=16 warm-up. One block = one warp = 32 chunks = a
// contiguous 1040-step span staged once into 8.7KB smem -> ~26 CTAs/SM.
// No __syncthreads at all (warp-synchronous); outputs kept in registers,
// then written back through the (reused) input smem for coalesced STG.

#define L_CHUNK 32
#define W_WARM  16
#define CPB     32                            // chunks (threads) per block
#define SPAN    (CPB * L_CHUNK + W_WARM)      // 1040 steps per block
#define NGRP    (SPAN / 4)                    // 260 float4 groups
#define NSTEP   (W_WARM + L_CHUNK)            // 48 steps per thread
#define NROWS   33                            // span rows (1040/32 -> 33)
#define PITCH   33                            // odd pitch: conflict-free

__global__ void __launch_bounds__(CPB, 24)
ricker_kernel(const float* __restrict__ N0,
              const float* __restrict__ Temp,
              const float* __restrict__ sigma,
              const float* __restrict__ eps,
              const float* __restrict__ mp,
              float* __restrict__ out,
              int S)   // S = T-1 steps
{
    // span entry i at sIn[i>>5][i&31]; after the chain this buffer is
    // reinterpreted as float rows for output staging (warp-private block).
    __shared__ float2 sIn[NROWS][PITCH];

    const int tid    = threadIdx.x;
    const int chunk0 = blockIdx.x * CPB;
    const int base   = chunk0 * L_CHUNK - W_WARM;  // global step of span[0]

    const float alpha = mp[0];
    const float beta  = mp[1];
    const float bx    = mp[2];
    const float cx    = mp[3];
    const float sg    = sigma[0];
    const float n0v   = N0[0];

    const float abx = alpha * bx;
    const float acx = alpha * cx;
    const float bc  = -alpha * beta;

    if (chunk0 == 0 && tid == 0) out[0] = n0v;

    // ---- stage the span: coalesced float4 loads, compute (a, e), STS ----
#pragma unroll
    for (int j = 0; j < 9; ++j) {
        const int p = tid + CPB * j;          // float4 group id
        if (p < NGRP) {
            const int i = 4 * p;              // span entry
            const int g = base + i;           // global step index
            float4 t4, e4;
            if (g >= 0 && g + 4 <= S) {
                t4 = *reinterpret_cast<const float4*>(Temp + g);
                e4 = *reinterpret_cast<const float4*>(eps  + g);
            } else {
                float tv[4], ev[4];
#pragma unroll
                for (int u = 0; u < 4; ++u) {
                    int gi = g + u;
                    gi = gi < 0 ? 0 : (gi > S - 1 ? S - 1 : gi);
                    tv[u] = Temp[gi];
                    ev[u] = eps[gi];
                }
                t4 = make_float4(tv[0], tv[1], tv[2], tv[3]);
                e4 = make_float4(ev[0], ev[1], ev[2], ev[3]);
            }
            float2* rp = &sIn[i >> 5][i & 31];  // 4 entries, one row
            rp[0] = make_float2(fmaf(t4.x, fmaf(t4.x, acx, abx), alpha), sg * e4.x);
            rp[1] = make_float2(fmaf(t4.y, fmaf(t4.y, acx, abx), alpha), sg * e4.y);
            rp[2] = make_float2(fmaf(t4.z, fmaf(t4.z, acx, abx), alpha), sg * e4.z);
            rp[3] = make_float2(fmaf(t4.w, fmaf(t4.w, acx, abx), alpha), sg * e4.w);
        }
    }
    __syncwarp();

    // ---- serial 48-step chain (16 warm + 32 live), outputs to registers ----
    const bool isC0 = (chunk0 + tid == 0);
    float ro[L_CHUNK];
    float n = 1.0f;                           // warm-up seed
#pragma unroll
    for (int s = 0; s < NSTEP; ++s) {
        if (s == W_WARM && isC0) n = n0v;     // chunk 0: exact start
        const float2 ae = (s < L_CHUNK) ? sIn[tid][s] : sIn[tid + 1][s - L_CHUNK];
        const float x = fmaf(bc, n, ae.x);    // alpha*(1 - beta*n + f)
        float p       = fmaf(x, 0.16666667f, 0.5f);
        p             = fmaf(x, p, 1.0f);
        p             = fmaf(x, p, 1.0f);     // ~exp(x), deg-3 Taylor
        n             = fmaf(n, p, ae.y);
        if (s >= W_WARM) ro[s - W_WARM] = n;
    }
    __syncwarp();                             // all chain reads of sIn done

    // ---- stage outputs into reused smem, then coalesced STG ----
    float* sO = reinterpret_cast<float*>(sIn);   // [32][33] float rows
#pragma unroll
    for (int s = 0; s < L_CHUNK; ++s)
        sO[tid * PITCH + s] = ro[s];
    __syncwarp();

    const int qbase = chunk0 * L_CHUNK;
#pragma unroll
    for (int j = 0; j < L_CHUNK; ++j) {
        const int e   = tid + CPB * j;        // 0..1023
        const int idx = qbase + e;            // global step index
        if (idx < S)
            out[idx + 1] = sO[j * PITCH + tid];
    }
}

extern "C" void kernel_launch(void* const* d_in, const int* in_sizes, int n_in,
                              void* d_out, int out_size) {
    const float* N0    = (const float*)d_in[0];
    const float* Temp  = (const float*)d_in[1];
    const float* sigma = (const float*)d_in[2];
    const float* eps   = (const float*)d_in[3];
    const float* mp    = (const float*)d_in[4];
    float* out = (float*)d_out;

    const int T = in_sizes[1];
    const int S = T - 1;
    const int C = (S + L_CHUNK - 1) / L_CHUNK;        // 131072
    const int blocks = (C + CPB - 1) / CPB;           // 4096

    ricker_kernel<<<blocks, CPB>>>(N0, Temp, sigma, eps, mp, out, S);
}